// round 1
// baseline (speedup 1.0000x reference)
#include <cuda_runtime.h>
#include <cuda_bf16.h>
#include <math.h>

#define NGOI 500
#define SUMH 224
#define SUMW 221

// Gene-level precomputed tables (per layer blocks).
// g_row[k] = {A_k = H_k * c_k,  bl_k}   (length n per gene per layer)
// g_bin[b] = {H_b, H_{b+1}, w_b, bl_b}  (length n-1 per gene per layer)
__device__ float2 g_row[NGOI * SUMH];   // 896 KB
__device__ float4 g_bin[NGOI * SUMW];   // 1.77 MB

// ---------------------------------------------------------------------------
// Precompute: one warp per (gene, layer). softmax(widths) -> w, cumsum -> bl,
// H = exp(uh), c_k = 0.5*(w_{k-1}+w_k) with boundary halves.
// ---------------------------------------------------------------------------
__global__ void precompute_kernel(const float* __restrict__ hw,
                                  const float* __restrict__ ww,
                                  const int* __restrict__ goi)
{
    const int NB[3]   = {128, 64, 32};
    const int WOFF[3] = {0, 127, 190};
    const int HOFF[3] = {0, 128, 192};
    const int ROFF[3] = {0, NGOI * 128, NGOI * 192};
    const int BOFF[3] = {0, NGOI * 127, NGOI * 190};

    int g = blockIdx.x;
    int l = blockIdx.y;
    int lane = threadIdx.x;
    int n = NB[l];
    int E = n >> 5;
    int gid = goi[g];
    const float* uw = ww + (size_t)gid * SUMW + WOFF[l];
    const float* uh = hw + (size_t)gid * SUMH + HOFF[l];

    __shared__ float sw[128];
    __shared__ float sbl[128];
    __shared__ float sH[128];
    const unsigned FM = 0xffffffffu;

    float u[4], ex[4];
    float m = -1e30f;
    for (int j = 0; j < E; j++) {
        int k = j * 32 + lane;
        u[j] = (k < n - 1) ? uw[k] : -1e30f;
        m = fmaxf(m, u[j]);
    }
    for (int o = 16; o; o >>= 1) m = fmaxf(m, __shfl_xor_sync(FM, m, o));

    float s = 0.f;
    for (int j = 0; j < E; j++) {
        int k = j * 32 + lane;
        ex[j] = (k < n - 1) ? expf(u[j] - m) : 0.f;
        s += ex[j];
    }
    for (int o = 16; o; o >>= 1) s += __shfl_xor_sync(FM, s, o);
    float inv = 1.f / s;

    // inclusive cumsum over k = j*32 + lane ordering
    float base = 0.f;
    for (int j = 0; j < E; j++) {
        int k = j * 32 + lane;
        float v = ex[j] * inv;            // w_k (0 for k == n-1 slot)
        float t = v;
        for (int o = 1; o < 32; o <<= 1) {
            float q = __shfl_up_sync(FM, t, o);
            if (lane >= o) t += q;
        }
        t += base;
        base = __shfl_sync(FM, t, 31);
        if (k < n - 1) { sw[k] = v; sbl[k + 1] = t; }
    }
    __syncwarp();
    if (lane == 0) { sbl[0] = 0.f; sbl[n - 1] = 1.0f; }  // ref forces last cumsum to 1
    __syncwarp();

    for (int j = 0; j < E; j++) {
        int k = j * 32 + lane;
        sH[k] = expf(uh[k]);
    }
    __syncwarp();

    float2* row = g_row + ROFF[l] + g * n;
    float4* bin = g_bin + BOFF[l] + g * (n - 1);
    for (int j = 0; j < E; j++) {
        int k = j * 32 + lane;
        float wkm1 = (k >= 1)     ? sw[k - 1] : 0.f;
        float wk   = (k < n - 1)  ? sw[k]     : 0.f;
        float c = 0.5f * (wkm1 + wk);
        row[k] = make_float2(sH[k] * c, sbl[k]);
        if (k < n - 1) bin[k] = make_float4(sH[k], sH[k + 1], sw[k], sbl[k]);
    }
}

// ---------------------------------------------------------------------------
// Main: one warp per point. bin_idx is warp-uniform -> ballot search,
// shfl extraction, butterfly reductions for (area, partial).
// ---------------------------------------------------------------------------
template <int N>
__device__ __forceinline__ void spline_layer(
    float& x, float& lad, int g, int lane,
    const float* __restrict__ dptr,
    const float2* __restrict__ rowbase,
    const float4* __restrict__ binbase)
{
    constexpr int E = N / 32;
    constexpr unsigned FM = 0xffffffffu;
    float A[E], bl[E], Ed[E];

    const float2* row = rowbase + g * N;
    if constexpr (E == 4) {
        const float4* rv = reinterpret_cast<const float4*>(row);
        float4 r0 = __ldg(rv + lane * 2);
        float4 r1 = __ldg(rv + lane * 2 + 1);
        A[0] = r0.x; bl[0] = r0.y; A[1] = r0.z; bl[1] = r0.w;
        A[2] = r1.x; bl[2] = r1.y; A[3] = r1.z; bl[3] = r1.w;
        float4 d = __ldg(reinterpret_cast<const float4*>(dptr) + lane);
        Ed[0] = __expf(d.x); Ed[1] = __expf(d.y);
        Ed[2] = __expf(d.z); Ed[3] = __expf(d.w);
    } else if constexpr (E == 2) {
        float4 r0 = __ldg(reinterpret_cast<const float4*>(row) + lane);
        A[0] = r0.x; bl[0] = r0.y; A[1] = r0.z; bl[1] = r0.w;
        float2 d = __ldg(reinterpret_cast<const float2*>(dptr) + lane);
        Ed[0] = __expf(d.x); Ed[1] = __expf(d.y);
    } else {
        float2 r0 = __ldg(row + lane);
        A[0] = r0.x; bl[0] = r0.y;
        Ed[0] = __expf(__ldg(dptr + lane));
    }

    // bin search: count of (x >= bl[k]) over all n boundaries; uniform result
    int cnt = 0;
#pragma unroll
    for (int j = 0; j < E; j++)
        cnt += __popc(__ballot_sync(FM, x >= bl[j]));
    int b = min(cnt - 1, N - 2);   // cnt >= 1 since bl[0] = 0 <= x

    // area = sum A*Ed ; partial = sum_{k<=b} A*Ed
    float full = 0.f, part = 0.f;
    int kbase = lane * E;
#pragma unroll
    for (int j = 0; j < E; j++) {
        float t = A[j] * Ed[j];
        full += t;
        if (kbase + j <= b) part += t;
    }
#pragma unroll
    for (int o = 16; o; o >>= 1) {
        full += __shfl_xor_sync(FM, full, o);
        part += __shfl_xor_sync(FM, part, o);
    }

    // extract Ed_b, Ed_{b+1}: owner lane = idx/E, local slot = idx%E (uniform b)
    int jb  = b & (E - 1);
    int jb1 = (b + 1) & (E - 1);
    float vb, vb1;
    if constexpr (E == 1) { vb = Ed[0]; vb1 = Ed[0]; }
    else if constexpr (E == 2) { vb = jb ? Ed[1] : Ed[0]; vb1 = jb1 ? Ed[1] : Ed[0]; }
    else {
        vb  = (jb  < 2) ? (jb  ? Ed[1] : Ed[0]) : ((jb  == 3) ? Ed[3] : Ed[2]);
        vb1 = (jb1 < 2) ? (jb1 ? Ed[1] : Ed[0]) : ((jb1 == 3) ? Ed[3] : Ed[2]);
    }
    constexpr int SH = (E == 4) ? 2 : ((E == 2) ? 1 : 0);
    float Edb  = __shfl_sync(FM, vb, b >> SH);
    float Edb1 = __shfl_sync(FM, vb1, (b + 1) >> SH);

    float4 sc = __ldg(binbase + g * (N - 1) + b);  // {H_b, H_{b+1}, w_b, bl_b}
    float ra  = __fdividef(1.f, full);
    float eb  = sc.x * Edb;
    float eb1 = sc.y * Edb1;
    float wb  = sc.z;
    float blb = sc.w;

    float in_cdf = (part - 0.5f * eb * wb) * ra;
    float hl = eb * ra;
    float hr = eb1 * ra;
    float alpha = __fdividef(x - blb, wb);
    float dhh = hr - hl;
    float out = fmaf(fmaf(0.5f * dhh * wb, alpha, hl * wb), alpha, in_cdf);
    out = fminf(fmaxf(out, 0.f), 1.f);
    lad += __logf(fmaf(alpha, dhh, hl));
    x = out;
}

__global__ __launch_bounds__(256) void spline_main(
    const float* __restrict__ xin,
    const float* __restrict__ delta,
    const int* __restrict__ lgi,
    float* __restrict__ out,
    int n_points)
{
    int warp = (blockIdx.x * blockDim.x + threadIdx.x) >> 5;
    if (warp >= n_points) return;
    int lane = threadIdx.x & 31;
    int p = warp;

    float x = __ldg(xin + p);
    int g = __ldg(lgi + p);
    float lad = 0.f;
    const float* dptr = delta + (size_t)p * SUMH;

    spline_layer<128>(x, lad, g, lane, dptr,       g_row,              g_bin);
    spline_layer<64> (x, lad, g, lane, dptr + 128, g_row + NGOI * 128, g_bin + NGOI * 127);
    spline_layer<32> (x, lad, g, lane, dptr + 192, g_row + NGOI * 192, g_bin + NGOI * 190);

    if (lane == 0) out[p] = x;
    if (lane == 1) out[n_points + p] = lad;
}

extern "C" void kernel_launch(void* const* d_in, const int* in_sizes, int n_in,
                              void* d_out, int out_size)
{
    const float* x     = (const float*)d_in[0];
    const float* delta = (const float*)d_in[1];
    const float* hw    = (const float*)d_in[2];
    const float* ww    = (const float*)d_in[3];
    const int*   goi   = (const int*)d_in[4];
    const int*   lgi   = (const int*)d_in[5];
    float* out = (float*)d_out;
    int n = in_sizes[0];

    dim3 pg(NGOI, 3);
    precompute_kernel<<<pg, 32>>>(hw, ww, goi);

    int blocks = (n * 32 + 255) / 256;   // one warp per point
    spline_main<<<blocks, 256>>>(x, delta, lgi, out, n);
}

// round 5
// speedup vs baseline: 2.2608x; 2.2608x over previous
#include <cuda_runtime.h>
#include <cuda_bf16.h>
#include <math.h>

#define NGOI 500
#define SUMH 224
#define SUMW 221

// Gene-level precomputed tables (per layer blocks).
// g_row[k] = {A_k = H_k * c_k,  bl_k}   (length n per gene per layer)
// g_bin[b] = {H_b, H_{b+1}, w_b, bl_b}  (length n-1 per gene per layer)
__device__ __align__(16) float2 g_row[NGOI * SUMH];   // 896 KB
__device__ __align__(16) float4 g_bin[NGOI * SUMW];   // 1.77 MB

// ---------------------------------------------------------------------------
// Precompute: one warp per (gene, layer). softmax(widths) -> w, cumsum -> bl,
// H = exp(uh), c_k = 0.5*(w_{k-1}+w_k).
// ---------------------------------------------------------------------------
__global__ void precompute_kernel(const float* __restrict__ hw,
                                  const float* __restrict__ ww,
                                  const int* __restrict__ goi)
{
    const int NB[3]   = {128, 64, 32};
    const int WOFF[3] = {0, 127, 190};
    const int HOFF[3] = {0, 128, 192};
    const int ROFF[3] = {0, NGOI * 128, NGOI * 192};
    const int BOFF[3] = {0, NGOI * 127, NGOI * 190};

    int g = blockIdx.x;
    int l = blockIdx.y;
    int lane = threadIdx.x;
    int n = NB[l];
    int E = n >> 5;
    int gid = goi[g];
    const float* uw = ww + (size_t)gid * SUMW + WOFF[l];
    const float* uh = hw + (size_t)gid * SUMH + HOFF[l];

    __shared__ float sw[128];
    __shared__ float sbl[128];
    __shared__ float sH[128];
    const unsigned FM = 0xffffffffu;

    float u[4], ex[4];
    float m = -1e30f;
    for (int j = 0; j < E; j++) {
        int k = j * 32 + lane;
        u[j] = (k < n - 1) ? uw[k] : -1e30f;
        m = fmaxf(m, u[j]);
    }
    for (int o = 16; o; o >>= 1) m = fmaxf(m, __shfl_xor_sync(FM, m, o));

    float s = 0.f;
    for (int j = 0; j < E; j++) {
        int k = j * 32 + lane;
        ex[j] = (k < n - 1) ? expf(u[j] - m) : 0.f;
        s += ex[j];
    }
    for (int o = 16; o; o >>= 1) s += __shfl_xor_sync(FM, s, o);
    float inv = 1.f / s;

    // inclusive cumsum over k = j*32 + lane ordering
    float base = 0.f;
    for (int j = 0; j < E; j++) {
        int k = j * 32 + lane;
        float v = ex[j] * inv;            // w_k (0 for k == n-1 slot)
        float t = v;
        for (int o = 1; o < 32; o <<= 1) {
            float q = __shfl_up_sync(FM, t, o);
            if (lane >= o) t += q;
        }
        t += base;
        base = __shfl_sync(FM, t, 31);
        if (k < n - 1) { sw[k] = v; sbl[k + 1] = t; }
    }
    __syncwarp();
    if (lane == 0) { sbl[0] = 0.f; sbl[n - 1] = 1.0f; }  // ref forces last cumsum to 1
    __syncwarp();

    for (int j = 0; j < E; j++) {
        int k = j * 32 + lane;
        sH[k] = expf(uh[k]);
    }
    __syncwarp();

    float2* row = g_row + ROFF[l] + g * n;
    float4* bin = g_bin + BOFF[l] + g * (n - 1);
    for (int j = 0; j < E; j++) {
        int k = j * 32 + lane;
        float wkm1 = (k >= 1)     ? sw[k - 1] : 0.f;
        float wk   = (k < n - 1)  ? sw[k]     : 0.f;
        float c = 0.5f * (wkm1 + wk);
        row[k] = make_float2(sH[k] * c, sbl[k]);
        if (k < n - 1) bin[k] = make_float4(sH[k], sH[k + 1], sw[k], sbl[k]);
    }
}

// ---------------------------------------------------------------------------
// Main: 8 lanes per point, 4 points per warp. Granule mapping:
// bin k = (j*8 + sl)*4 + i  (i in 0..3). Per-lane state = granule sums only;
// the b-granule's partial terms are recomputed from L1 in the epilogue.
// ---------------------------------------------------------------------------
template <int N>
__device__ __forceinline__ void spline_layer(
    float& x, float& lad, int g, int sl,
    const float* __restrict__ dptr,
    const float2* __restrict__ rowbase,
    const float4* __restrict__ binbase)
{
    constexpr int Gn = N / 32;           // granules per lane
    constexpr unsigned FM = 0xffffffffu;

    const float2* row = rowbase + g * N;
    float gs[Gn];
    int cnt = 0;

#pragma unroll
    for (int j = 0; j < Gn; j++) {
        int kb = (j * 8 + sl) * 4;
        float4 r0 = __ldg(reinterpret_cast<const float4*>(row + kb));      // {A,bl,A,bl}
        float4 r1 = __ldg(reinterpret_cast<const float4*>(row + kb) + 1);
        float4 d  = __ldg(reinterpret_cast<const float4*>(dptr + kb));
        float t0 = r0.x * __expf(d.x);
        float t1 = r0.z * __expf(d.y);
        float t2 = r1.x * __expf(d.z);
        float t3 = r1.z * __expf(d.w);
        gs[j] = (t0 + t1) + (t2 + t3);
        cnt += (x >= r0.y) + (x >= r0.w) + (x >= r1.y) + (x >= r1.w);
    }

    float full = gs[0];
#pragma unroll
    for (int j = 1; j < Gn; j++) full += gs[j];

    // segmented (width-8) butterfly: count + full area
#pragma unroll
    for (int o = 4; o; o >>= 1) {
        cnt  += __shfl_xor_sync(FM, cnt, o);
        full += __shfl_xor_sync(FM, full, o);
    }
    int b = min(cnt - 1, N - 2);         // cnt >= 1 since bl[0] = 0 <= x
    int kb0 = b & ~3;                    // base bin of b's granule (uniform/segment)

    // partial cdf: granules strictly before b's granule
    float part = 0.f;
#pragma unroll
    for (int j = 0; j < Gn; j++) {
        int kb = (j * 8 + sl) * 4;
        if (kb < kb0) part += gs[j];
    }
#pragma unroll
    for (int o = 4; o; o >>= 1) part += __shfl_xor_sync(FM, part, o);

    // recompute b-granule terms from L1-hot lines (uniform per segment)
    float4 r0 = __ldg(reinterpret_cast<const float4*>(row + kb0));
    float4 r1 = __ldg(reinterpret_cast<const float4*>(row + kb0) + 1);
    float4 d  = __ldg(reinterpret_cast<const float4*>(dptr + kb0));
    int r = b & 3;
    float e0 = __expf(d.x), e1 = __expf(d.y), e2 = __expf(d.z), e3 = __expf(d.w);
    part += r0.x * e0;                       // k = kb0 <= b always
    if (r >= 1) part += r0.z * e1;
    if (r >= 2) part += r1.x * e2;
    if (r >= 3) part += r1.z * e3;

    // exp(delta) at bins b and b+1
    float edb  = (r < 2) ? (r ? e1 : e0) : ((r == 3) ? e3 : e2);
    float edb1;
    if (r < 3) edb1 = (r == 0) ? e1 : ((r == 1) ? e2 : e3);
    else       edb1 = __expf(__ldg(dptr + b + 1));   // b+1 <= N-1, next granule

    float4 sc = __ldg(binbase + g * (N - 1) + b);    // {H_b, H_{b+1}, w_b, bl_b}
    float ra  = __fdividef(1.f, full);
    float eb  = sc.x * edb;
    float eb1 = sc.y * edb1;
    float wb  = sc.z;
    float blb = sc.w;

    float in_cdf = (part - 0.5f * eb * wb) * ra;
    float hl = eb * ra;
    float hr = eb1 * ra;
    float alpha = __fdividef(x - blb, wb);
    float dhh = hr - hl;
    float out = fmaf(fmaf(0.5f * dhh * wb, alpha, hl * wb), alpha, in_cdf);
    out = fminf(fmaxf(out, 0.f), 1.f);
    lad += __logf(fmaf(alpha, dhh, hl));
    x = out;
}

__global__ __launch_bounds__(256) void spline_main(
    const float* __restrict__ xin,
    const float* __restrict__ delta,
    const int* __restrict__ lgi,
    float* __restrict__ out,
    int n_points)
{
    int warp = (blockIdx.x * blockDim.x + threadIdx.x) >> 5;
    int lane = threadIdx.x & 31;
    int seg  = lane >> 3;        // 0..3 : point within warp
    int sl   = lane & 7;         // 0..7 : lane within point

    int p = warp * 4 + seg;
    int nwarps = (n_points + 3) >> 2;
    if (warp >= nwarps) return;              // whole warp exits together
    int pc = min(p, n_points - 1);           // clamp: keep all lanes converged

    float x = __ldg(xin + pc);
    int g = __ldg(lgi + pc);
    float lad = 0.f;
    const float* dptr = delta + (size_t)pc * SUMH;

    spline_layer<128>(x, lad, g, sl, dptr,       g_row,              g_bin);
    spline_layer<64> (x, lad, g, sl, dptr + 128, g_row + NGOI * 128, g_bin + NGOI * 127);
    spline_layer<32> (x, lad, g, sl, dptr + 192, g_row + NGOI * 192, g_bin + NGOI * 190);

    if (p < n_points) {
        if (sl == 0) out[p] = x;
        if (sl == 1) out[n_points + p] = lad;
    }
}

extern "C" void kernel_launch(void* const* d_in, const int* in_sizes, int n_in,
                              void* d_out, int out_size)
{
    const float* x     = (const float*)d_in[0];
    const float* delta = (const float*)d_in[1];
    const float* hw    = (const float*)d_in[2];
    const float* ww    = (const float*)d_in[3];
    const int*   goi   = (const int*)d_in[4];
    const int*   lgi   = (const int*)d_in[5];
    float* out = (float*)d_out;
    int n = in_sizes[0];

    dim3 pg(NGOI, 3);
    precompute_kernel<<<pg, 32>>>(hw, ww, goi);

    int nwarps = (n + 3) / 4;                 // 4 points per warp
    int blocks = (nwarps * 32 + 255) / 256;
    spline_main<<<blocks, 256>>>(x, delta, lgi, out, n);
}